// round 6
// baseline (speedup 1.0000x reference)
#include <cuda_runtime.h>
#include <math.h>

#define N_NODES 100000
#define N_NNZ   1000000
#define F_IN    1433
#define F_HID   128
#define F_OUT   64
#define N_POS   20000
#define N_NEG   20000
#define N_EDGES (N_POS + N_NEG)
#define EPS     1e-6f

// ---------------- scratch (static __device__, no allocation) ----------------
__device__ float g_x[(size_t)N_NODES * F_HID];        // layer input / pairnorm output
__device__ float g_support[(size_t)N_NODES * F_HID];  // GEMM output
__device__ float g_h[(size_t)N_NODES * F_HID];        // spmm+relu output
__device__ int   g_rowptr[N_NODES + 1];
__device__ int   g_cnt[N_NODES];                      // counts, then running offsets
__device__ int   g_bsum[128];
__device__ int   g_col[N_NNZ];
__device__ float g_val[N_NNZ];
__device__ float g_colsum[F_HID];

#define SCAN_NB ((N_NODES + 1023) / 1024)             // 98

// ---------------- CSR build ----------------
__global__ void zero_cnt_k() {
    int i = blockIdx.x * blockDim.x + threadIdx.x;
    if (i < N_NODES) g_cnt[i] = 0;
}

__global__ void hist_k(const int* __restrict__ row) {
    int i = blockIdx.x * blockDim.x + threadIdx.x;
    if (i < N_NNZ) atomicAdd(&g_cnt[row[i]], 1);
}

__global__ void scanA_k() {
    __shared__ int sm[1024];
    int t = threadIdx.x;
    int i = blockIdx.x * 1024 + t;
    int v = (i < N_NODES) ? g_cnt[i] : 0;
    sm[t] = v;
    __syncthreads();
#pragma unroll
    for (int off = 1; off < 1024; off <<= 1) {
        int add = (t >= off) ? sm[t - off] : 0;
        __syncthreads();
        sm[t] += add;
        __syncthreads();
    }
    if (i < N_NODES) g_rowptr[i] = sm[t] - v;  // exclusive within block
    if (t == 1023) g_bsum[blockIdx.x] = sm[1023];
}

__global__ void scanB_k() {
    if (threadIdx.x == 0) {
        int run = 0;
        for (int b = 0; b < SCAN_NB; b++) {
            int v = g_bsum[b];
            g_bsum[b] = run;
            run += v;
        }
    }
}

__global__ void scanC_k() {
    int i = blockIdx.x * 1024 + threadIdx.x;
    if (i < N_NODES) {
        int v = g_rowptr[i] + g_bsum[blockIdx.x];
        g_rowptr[i] = v;
        g_cnt[i] = v;  // running offsets for scatter
    }
    if (i == 0) g_rowptr[N_NODES] = N_NNZ;
}

__global__ void scatter_k(const int* __restrict__ row, const int* __restrict__ col,
                          const float* __restrict__ val) {
    int i = blockIdx.x * blockDim.x + threadIdx.x;
    if (i < N_NNZ) {
        int r = row[i];
        int p = atomicAdd(&g_cnt[r], 1);
        g_col[p] = col[i];
        g_val[p] = val[i];
    }
}

// ---------------- fp32 SGEMM: C[M,N] = A[M,K] @ B[K,N] ----------------
#define BM 128
#define BN 128
#define BK 16
#define TM 8
#define TN 8

__global__ __launch_bounds__(256, 2)
void sgemm_k(const float* __restrict__ A, const float* __restrict__ B,
             float* __restrict__ C, int M, int N, int K) {
    __shared__ float As[BK][BM + 4];
    __shared__ float Bs[BK][BN];
    int tid = threadIdx.x;
    int block_row = blockIdx.x * BM;
    int ty = tid >> 4;        // 0..15
    int tx = tid & 15;        // 0..15

    float acc[TM][TN];
#pragma unroll
    for (int i = 0; i < TM; i++)
#pragma unroll
        for (int j = 0; j < TN; j++) acc[i][j] = 0.f;

    for (int k0 = 0; k0 < K; k0 += BK) {
        // load A tile: BM x BK (row-major, lda=K), store transposed As[k][m]
#pragma unroll
        for (int i = 0; i < 8; i++) {
            int idx = tid + i * 256;        // 0..2047
            int r = idx >> 4;               // 0..127
            int kk = idx & 15;
            int gr = block_row + r;
            int gk = k0 + kk;
            float v = 0.f;
            if (gr < M && gk < K) v = A[(size_t)gr * K + gk];
            As[kk][r] = v;
        }
        // load B tile: BK x BN (row-major, ldb=N)
#pragma unroll
        for (int i = 0; i < 8; i++) {
            int idx = tid + i * 256;
            int kk = idx >> 7;              // 0..15
            int c = idx & 127;
            int gk = k0 + kk;
            float v = 0.f;
            if (gk < K && c < N) v = B[(size_t)gk * N + c];
            Bs[kk][c] = v;
        }
        __syncthreads();
#pragma unroll
        for (int kk = 0; kk < BK; kk++) {
            float a[TM], b[TN];
#pragma unroll
            for (int i = 0; i < TM; i++) a[i] = As[kk][ty * TM + i];
#pragma unroll
            for (int j = 0; j < TN; j++) b[j] = Bs[kk][tx * TN + j];
#pragma unroll
            for (int i = 0; i < TM; i++)
#pragma unroll
                for (int j = 0; j < TN; j++) acc[i][j] = fmaf(a[i], b[j], acc[i][j]);
        }
        __syncthreads();
    }

#pragma unroll
    for (int i = 0; i < TM; i++) {
        int gr = block_row + ty * TM + i;
        if (gr >= M) continue;
#pragma unroll
        for (int j = 0; j < TN; j++) {
            int gc = tx * TN + j;
            if (gc < N) C[(size_t)gr * N + gc] = acc[i][j];
        }
    }
}

// ---------------- SpMM (CSR) + bias + ReLU : one warp per row ----------------
template <int F>
__global__ void spmm_relu_k(const float* __restrict__ bias) {
    constexpr int VEC = F / 32;
    int w = (blockIdx.x * blockDim.x + threadIdx.x) >> 5;
    if (w >= N_NODES) return;
    int lane = threadIdx.x & 31;

    float acc[VEC];
#pragma unroll
    for (int v = 0; v < VEC; v++) acc[v] = 0.f;

    int s = g_rowptr[w], e = g_rowptr[w + 1];
    const float* base = g_support;
    for (int j = s; j < e; j++) {
        int c = __ldg(&g_col[j]);
        float vv = __ldg(&g_val[j]);
        const float* p = base + (size_t)c * F + lane * VEC;
        if (VEC == 4) {
            float4 q = *reinterpret_cast<const float4*>(p);
            acc[0] += vv * q.x; acc[1] += vv * q.y;
            acc[2] += vv * q.z; acc[3] += vv * q.w;
        } else {
            float2 q = *reinterpret_cast<const float2*>(p);
            acc[0] += vv * q.x; acc[1] += vv * q.y;
        }
    }

    float* out = g_h + (size_t)w * F + lane * VEC;
    if (VEC == 4) {
        float4 b = *reinterpret_cast<const float4*>(bias + lane * 4);
        float4 r;
        r.x = fmaxf(acc[0] + b.x, 0.f);
        r.y = fmaxf(acc[1] + b.y, 0.f);
        r.z = fmaxf(acc[2] + b.z, 0.f);
        r.w = fmaxf(acc[3] + b.w, 0.f);
        *reinterpret_cast<float4*>(out) = r;
    } else {
        float2 b = *reinterpret_cast<const float2*>(bias + lane * 2);
        float2 r;
        r.x = fmaxf(acc[0] + b.x, 0.f);
        r.y = fmaxf(acc[1] + b.y, 0.f);
        *reinterpret_cast<float2*>(out) = r;
    }
}

// ---------------- column sums (for PairNorm mean) ----------------
__global__ void zero_colsum_k() {
    if (threadIdx.x < F_HID) g_colsum[threadIdx.x] = 0.f;
}

template <int F>
__global__ void colsum_k() {
    int f = threadIdx.x;  // blockDim.x == F
    float s = 0.f;
    for (int r = blockIdx.x; r < N_NODES; r += gridDim.x)
        s += g_h[(size_t)r * F + f];
    atomicAdd(&g_colsum[f], s);
}

// ---------------- PairNorm (PN-SI): center cols, per-row L2 normalize ---------
template <int F>
__global__ void pairnorm_k() {
    constexpr int VEC = F / 32;
    int w = (blockIdx.x * blockDim.x + threadIdx.x) >> 5;
    if (w >= N_NODES) return;
    int lane = threadIdx.x & 31;

    float v[VEC];
    const float* src = g_h + (size_t)w * F + lane * VEC;
    if (VEC == 4) {
        float4 q = *reinterpret_cast<const float4*>(src);
        v[0] = q.x; v[1] = q.y; v[2] = q.z; v[3] = q.w;
    } else {
        float2 q = *reinterpret_cast<const float2*>(src);
        v[0] = q.x; v[1] = q.y;
    }
    const float invN = 1.0f / (float)N_NODES;
    float ss = 0.f;
#pragma unroll
    for (int i = 0; i < VEC; i++) {
        float m = g_colsum[lane * VEC + i] * invN;
        v[i] -= m;
        ss += v[i] * v[i];
    }
#pragma unroll
    for (int off = 16; off > 0; off >>= 1)
        ss += __shfl_xor_sync(0xFFFFFFFFu, ss, off);
    float inv = 1.0f / sqrtf(EPS + ss);

    float* dst = g_x + (size_t)w * F + lane * VEC;
    if (VEC == 4) {
        float4 r; r.x = v[0] * inv; r.y = v[1] * inv; r.z = v[2] * inv; r.w = v[3] * inv;
        *reinterpret_cast<float4*>(dst) = r;
    } else {
        float2 r; r.x = v[0] * inv; r.y = v[1] * inv;
        *reinterpret_cast<float2*>(dst) = r;
    }
}

// ---------------- decode: sigmoid(dot(x[s], x[d])), F_OUT=64 ----------------
__global__ void decode_k(const int* __restrict__ pos, const int* __restrict__ neg,
                         float* __restrict__ out) {
    int w = (blockIdx.x * blockDim.x + threadIdx.x) >> 5;
    if (w >= N_EDGES) return;
    int lane = threadIdx.x & 31;
    int s, d;
    if (w < N_POS) { s = pos[2 * w]; d = pos[2 * w + 1]; }
    else { int e = w - N_POS; s = neg[2 * e]; d = neg[2 * e + 1]; }
    float2 a = *reinterpret_cast<const float2*>(g_x + (size_t)s * F_OUT + lane * 2);
    float2 b = *reinterpret_cast<const float2*>(g_x + (size_t)d * F_OUT + lane * 2);
    float p = a.x * b.x + a.y * b.y;
#pragma unroll
    for (int off = 16; off > 0; off >>= 1)
        p += __shfl_xor_sync(0xFFFFFFFFu, p, off);
    if (lane == 0) out[w] = 1.0f / (1.0f + expf(-p));
}

// ---------------- launch ----------------
extern "C" void kernel_launch(void* const* d_in, const int* in_sizes, int n_in,
                              void* d_out, int out_size) {
    const float* in_feature = (const float*)d_in[0];
    const int*   adj_row    = (const int*)d_in[1];
    const int*   adj_col    = (const int*)d_in[2];
    const float* adj_val    = (const float*)d_in[3];
    const int*   pos_ei     = (const int*)d_in[4];
    const int*   neg_ei     = (const int*)d_in[5];
    const float* W0 = (const float*)d_in[6];
    const float* b0 = (const float*)d_in[7];
    const float* W1 = (const float*)d_in[8];
    const float* b1 = (const float*)d_in[9];
    const float* W2 = (const float*)d_in[10];
    const float* b2 = (const float*)d_in[11];
    float* out = (float*)d_out;

    float *g_x_p, *g_support_p;
    cudaGetSymbolAddress((void**)&g_x_p, g_x);
    cudaGetSymbolAddress((void**)&g_support_p, g_support);

    // --- CSR build ---
    zero_cnt_k<<<(N_NODES + 255) / 256, 256>>>();
    hist_k<<<(N_NNZ + 255) / 256, 256>>>(adj_row);
    scanA_k<<<SCAN_NB, 1024>>>();
    scanB_k<<<1, 32>>>();
    scanC_k<<<SCAN_NB, 1024>>>();
    scatter_k<<<(N_NNZ + 255) / 256, 256>>>(adj_row, adj_col, adj_val);

    const int gemm_grid = (N_NODES + BM - 1) / BM;          // 782
    const int warp_grid = (N_NODES * 32 + 255) / 256;       // 12500

    // --- layer 0: in_feature[N,1433] @ W0[1433,128] ---
    sgemm_k<<<gemm_grid, 256>>>(in_feature, W0, g_support_p, N_NODES, F_HID, F_IN);
    spmm_relu_k<F_HID><<<warp_grid, 256>>>(b0);
    zero_colsum_k<<<1, 128>>>();
    colsum_k<F_HID><<<512, F_HID>>>();
    pairnorm_k<F_HID><<<warp_grid, 256>>>();

    // --- layer 1: g_x[N,128] @ W1[128,128] ---
    sgemm_k<<<gemm_grid, 256>>>(g_x_p, W1, g_support_p, N_NODES, F_HID, F_HID);
    spmm_relu_k<F_HID><<<warp_grid, 256>>>(b1);
    zero_colsum_k<<<1, 128>>>();
    colsum_k<F_HID><<<512, F_HID>>>();
    pairnorm_k<F_HID><<<warp_grid, 256>>>();

    // --- layer 2: g_x[N,128] @ W2[128,64] ---
    sgemm_k<<<gemm_grid, 256>>>(g_x_p, W2, g_support_p, N_NODES, F_OUT, F_HID);
    spmm_relu_k<F_OUT><<<warp_grid, 256>>>(b2);
    zero_colsum_k<<<1, 128>>>();
    colsum_k<F_OUT><<<512, F_OUT>>>();
    pairnorm_k<F_OUT><<<warp_grid, 256>>>();

    // --- decode ---
    decode_k<<<(N_EDGES * 32 + 255) / 256, 256>>>(pos_ei, neg_ei, out);
}

// round 9
// speedup vs baseline: 1.2738x; 1.2738x over previous
#include <cuda_runtime.h>
#include <cuda_bf16.h>
#include <mma.h>
#include <math.h>

using namespace nvcuda;

#define N_NODES 100000
#define M_PAD   100096           // padded rows so wmma stores never go OOB
#define N_NNZ   1000000
#define F_IN    1433
#define F_HID   128
#define F_OUT   64
#define N_POS   20000
#define N_NEG   20000
#define N_EDGES (N_POS + N_NEG)
#define EPS     1e-6f

// ---------------- scratch (static __device__, no allocation) ----------------
__device__ float g_x[(size_t)M_PAD * F_HID];          // layer input / pairnorm output
__device__ float g_support[(size_t)M_PAD * F_HID];    // GEMM output (padded rows)
__device__ float g_h[(size_t)N_NODES * F_HID];        // spmm+relu output
__device__ int   g_rowptr[N_NODES + 1];
__device__ int   g_cnt[N_NODES];
__device__ int   g_bsum[128];
__device__ int   g_col[N_NNZ];
__device__ float g_val[N_NNZ];
__device__ float g_colsum[F_HID];

#define SCAN_NB ((N_NODES + 1023) / 1024)             // 98

// ---------------- CSR build ----------------
__global__ void zero_cnt_k() {
    int i = blockIdx.x * blockDim.x + threadIdx.x;
    if (i < N_NODES) g_cnt[i] = 0;
}

__global__ void hist_k(const int* __restrict__ row) {
    int i = blockIdx.x * blockDim.x + threadIdx.x;
    if (i < N_NNZ) atomicAdd(&g_cnt[row[i]], 1);
}

__global__ void scanA_k() {
    __shared__ int sm[1024];
    int t = threadIdx.x;
    int i = blockIdx.x * 1024 + t;
    int v = (i < N_NODES) ? g_cnt[i] : 0;
    sm[t] = v;
    __syncthreads();
#pragma unroll
    for (int off = 1; off < 1024; off <<= 1) {
        int add = (t >= off) ? sm[t - off] : 0;
        __syncthreads();
        sm[t] += add;
        __syncthreads();
    }
    if (i < N_NODES) g_rowptr[i] = sm[t] - v;
    if (t == 1023) g_bsum[blockIdx.x] = sm[1023];
}

__global__ void scanB_k() {
    if (threadIdx.x == 0) {
        int run = 0;
        for (int b = 0; b < SCAN_NB; b++) {
            int v = g_bsum[b];
            g_bsum[b] = run;
            run += v;
        }
    }
}

__global__ void scanC_k() {
    int i = blockIdx.x * 1024 + threadIdx.x;
    if (i < N_NODES) {
        int v = g_rowptr[i] + g_bsum[blockIdx.x];
        g_rowptr[i] = v;
        g_cnt[i] = v;
    }
    if (i == 0) g_rowptr[N_NODES] = N_NNZ;
}

__global__ void scatter_k(const int* __restrict__ row, const int* __restrict__ col,
                          const float* __restrict__ val) {
    int i = blockIdx.x * blockDim.x + threadIdx.x;
    if (i < N_NNZ) {
        int r = row[i];
        int p = atomicAdd(&g_cnt[r], 1);
        g_col[p] = col[i];
        g_val[p] = val[i];
    }
}

// ---------------- bf16-split tensor-core GEMM ----------------
// C[M_pad, NT] = A[M, K] @ B[K, NT], fp32 in/out, computed as
//   Ah*Bh + Ah*Bl + Al*Bh  with on-the-fly hi/lo bf16 splitting in SMEM.
// Block tile 128 x NT, 8 warps (4 row-groups x 2 col-groups), BK = 16.
// NT is the exact N of the weight matrix (128 or 64), so no N guards needed.
template <int NT>
__global__ __launch_bounds__(256)
void gemm_tc_k(const float* __restrict__ A, const float* __restrict__ B,
               float* __restrict__ C, int M, int K) {
    constexpr int BK  = 16;
    constexpr int WN  = NT / 2;       // warp col width (64 or 32)
    constexpr int NF  = WN / 16;      // b-fragments per warp (4 or 2)
    constexpr int LDA = BK + 8;       // 24 elts = 48B rows (16B aligned)
    constexpr int LDB = NT + 8;       // 136/72 elts (16B aligned)

    __shared__ __nv_bfloat16 Ah[128][LDA], Al[128][LDA];
    __shared__ __nv_bfloat16 Bh[BK][LDB], Bl[BK][LDB];

    int tid  = threadIdx.x;
    int warp = tid >> 5;
    int wr   = warp & 3;              // warp row group: 32 rows each
    int wc   = warp >> 2;             // warp col group: WN cols each
    int row0 = blockIdx.x * 128;

    wmma::fragment<wmma::accumulator, 16, 16, 16, float> acc[2][NF];
#pragma unroll
    for (int i = 0; i < 2; i++)
#pragma unroll
        for (int j = 0; j < NF; j++) wmma::fill_fragment(acc[i][j], 0.f);

    for (int k0 = 0; k0 < K; k0 += BK) {
        // --- stage A tile (128 x 16) with hi/lo split ---
#pragma unroll
        for (int t = 0; t < 8; t++) {
            int idx = tid + t * 256;          // 0..2047
            int r = idx >> 4, c = idx & 15;
            int gr = row0 + r, gk = k0 + c;
            float v = (gr < M && gk < K) ? A[(size_t)gr * K + gk] : 0.f;
            __nv_bfloat16 h = __float2bfloat16(v);
            Ah[r][c] = h;
            Al[r][c] = __float2bfloat16(v - __bfloat162float(h));
        }
        // --- stage B tile (16 x NT) with hi/lo split ---
#pragma unroll
        for (int t = 0; t < (BK * NT) / 256; t++) {
            int idx = tid + t * 256;
            int r = idx / NT, c = idx % NT;
            int gk = k0 + r;
            float v = (gk < K) ? B[(size_t)gk * NT + c] : 0.f;
            __nv_bfloat16 h = __float2bfloat16(v);
            Bh[r][c] = h;
            Bl[r][c] = __float2bfloat16(v - __bfloat162float(h));
        }
        __syncthreads();

        wmma::fragment<wmma::matrix_a, 16, 16, 16, __nv_bfloat16, wmma::row_major> afh[2], afl[2];
        wmma::fragment<wmma::matrix_b, 16, 16, 16, __nv_bfloat16, wmma::row_major> bfh[NF], bfl[NF];
#pragma unroll
        for (int i = 0; i < 2; i++) {
            int r = wr * 32 + i * 16;
            wmma::load_matrix_sync(afh[i], &Ah[r][0], LDA);
            wmma::load_matrix_sync(afl[i], &Al[r][0], LDA);
        }
#pragma unroll
        for (int j = 0; j < NF; j++) {
            int c = wc * WN + j * 16;
            wmma::load_matrix_sync(bfh[j], &Bh[0][c], LDB);
            wmma::load_matrix_sync(bfl[j], &Bl[0][c], LDB);
        }
#pragma unroll
        for (int i = 0; i < 2; i++)
#pragma unroll
            for (int j = 0; j < NF; j++) {
                wmma::mma_sync(acc[i][j], afl[i], bfh[j], acc[i][j]);
                wmma::mma_sync(acc[i][j], afh[i], bfl[j], acc[i][j]);
                wmma::mma_sync(acc[i][j], afh[i], bfh[j], acc[i][j]);
            }
        __syncthreads();
    }

    // --- store (C is padded to M_PAD rows, so no M guard needed) ---
#pragma unroll
    for (int i = 0; i < 2; i++)
#pragma unroll
        for (int j = 0; j < NF; j++) {
            int r = row0 + wr * 32 + i * 16;
            int c = wc * WN + j * 16;
            wmma::store_matrix_sync(&C[(size_t)r * NT + c], acc[i][j], NT, wmma::mem_row_major);
        }
}

// ---------------- SpMM (CSR) + bias + ReLU : one warp per row ----------------
template <int F>
__global__ void spmm_relu_k(const float* __restrict__ bias) {
    constexpr int VEC = F / 32;
    int w = (blockIdx.x * blockDim.x + threadIdx.x) >> 5;
    if (w >= N_NODES) return;
    int lane = threadIdx.x & 31;

    float acc[VEC];
#pragma unroll
    for (int v = 0; v < VEC; v++) acc[v] = 0.f;

    int s = g_rowptr[w], e = g_rowptr[w + 1];
    const float* base = g_support;
    for (int j = s; j < e; j++) {
        int c = __ldg(&g_col[j]);
        float vv = __ldg(&g_val[j]);
        const float* p = base + (size_t)c * F + lane * VEC;
        if (VEC == 4) {
            float4 q = *reinterpret_cast<const float4*>(p);
            acc[0] += vv * q.x; acc[1] += vv * q.y;
            acc[2] += vv * q.z; acc[3] += vv * q.w;
        } else {
            float2 q = *reinterpret_cast<const float2*>(p);
            acc[0] += vv * q.x; acc[1] += vv * q.y;
        }
    }

    float* out = g_h + (size_t)w * F + lane * VEC;
    if (VEC == 4) {
        float4 b = *reinterpret_cast<const float4*>(bias + lane * 4);
        float4 r;
        r.x = fmaxf(acc[0] + b.x, 0.f);
        r.y = fmaxf(acc[1] + b.y, 0.f);
        r.z = fmaxf(acc[2] + b.z, 0.f);
        r.w = fmaxf(acc[3] + b.w, 0.f);
        *reinterpret_cast<float4*>(out) = r;
    } else {
        float2 b = *reinterpret_cast<const float2*>(bias + lane * 2);
        float2 r;
        r.x = fmaxf(acc[0] + b.x, 0.f);
        r.y = fmaxf(acc[1] + b.y, 0.f);
        *reinterpret_cast<float2*>(out) = r;
    }
}

// ---------------- column sums (for PairNorm mean) ----------------
__global__ void zero_colsum_k() {
    if (threadIdx.x < F_HID) g_colsum[threadIdx.x] = 0.f;
}

template <int F>
__global__ void colsum_k() {
    int f = threadIdx.x;
    float s = 0.f;
    for (int r = blockIdx.x; r < N_NODES; r += gridDim.x)
        s += g_h[(size_t)r * F + f];
    atomicAdd(&g_colsum[f], s);
}

// ---------------- PairNorm (PN-SI) ----------------
template <int F>
__global__ void pairnorm_k() {
    constexpr int VEC = F / 32;
    int w = (blockIdx.x * blockDim.x + threadIdx.x) >> 5;
    if (w >= N_NODES) return;
    int lane = threadIdx.x & 31;

    float v[VEC];
    const float* src = g_h + (size_t)w * F + lane * VEC;
    if (VEC == 4) {
        float4 q = *reinterpret_cast<const float4*>(src);
        v[0] = q.x; v[1] = q.y; v[2] = q.z; v[3] = q.w;
    } else {
        float2 q = *reinterpret_cast<const float2*>(src);
        v[0] = q.x; v[1] = q.y;
    }
    const float invN = 1.0f / (float)N_NODES;
    float ss = 0.f;
#pragma unroll
    for (int i = 0; i < VEC; i++) {
        float m = g_colsum[lane * VEC + i] * invN;
        v[i] -= m;
        ss += v[i] * v[i];
    }
#pragma unroll
    for (int off = 16; off > 0; off >>= 1)
        ss += __shfl_xor_sync(0xFFFFFFFFu, ss, off);
    float inv = 1.0f / sqrtf(EPS + ss);

    float* dst = g_x + (size_t)w * F + lane * VEC;
    if (VEC == 4) {
        float4 r; r.x = v[0] * inv; r.y = v[1] * inv; r.z = v[2] * inv; r.w = v[3] * inv;
        *reinterpret_cast<float4*>(dst) = r;
    } else {
        float2 r; r.x = v[0] * inv; r.y = v[1] * inv;
        *reinterpret_cast<float2*>(dst) = r;
    }
}

// ---------------- decode ----------------
__global__ void decode_k(const int* __restrict__ pos, const int* __restrict__ neg,
                         float* __restrict__ out) {
    int w = (blockIdx.x * blockDim.x + threadIdx.x) >> 5;
    if (w >= N_EDGES) return;
    int lane = threadIdx.x & 31;
    int s, d;
    if (w < N_POS) { s = pos[2 * w]; d = pos[2 * w + 1]; }
    else { int e = w - N_POS; s = neg[2 * e]; d = neg[2 * e + 1]; }
    float2 a = *reinterpret_cast<const float2*>(g_x + (size_t)s * F_OUT + lane * 2);
    float2 b = *reinterpret_cast<const float2*>(g_x + (size_t)d * F_OUT + lane * 2);
    float p = a.x * b.x + a.y * b.y;
#pragma unroll
    for (int off = 16; off > 0; off >>= 1)
        p += __shfl_xor_sync(0xFFFFFFFFu, p, off);
    if (lane == 0) out[w] = 1.0f / (1.0f + expf(-p));
}

// ---------------- launch ----------------
extern "C" void kernel_launch(void* const* d_in, const int* in_sizes, int n_in,
                              void* d_out, int out_size) {
    const float* in_feature = (const float*)d_in[0];
    const int*   adj_row    = (const int*)d_in[1];
    const int*   adj_col    = (const int*)d_in[2];
    const float* adj_val    = (const float*)d_in[3];
    const int*   pos_ei     = (const int*)d_in[4];
    const int*   neg_ei     = (const int*)d_in[5];
    const float* W0 = (const float*)d_in[6];
    const float* b0 = (const float*)d_in[7];
    const float* W1 = (const float*)d_in[8];
    const float* b1 = (const float*)d_in[9];
    const float* W2 = (const float*)d_in[10];
    const float* b2 = (const float*)d_in[11];
    float* out = (float*)d_out;

    float *g_x_p, *g_support_p;
    cudaGetSymbolAddress((void**)&g_x_p, g_x);
    cudaGetSymbolAddress((void**)&g_support_p, g_support);

    // --- CSR build ---
    zero_cnt_k<<<(N_NODES + 255) / 256, 256>>>();
    hist_k<<<(N_NNZ + 255) / 256, 256>>>(adj_row);
    scanA_k<<<SCAN_NB, 1024>>>();
    scanB_k<<<1, 32>>>();
    scanC_k<<<SCAN_NB, 1024>>>();
    scatter_k<<<(N_NNZ + 255) / 256, 256>>>(adj_row, adj_col, adj_val);

    const int gemm_grid = (N_NODES + 127) / 128;            // 782
    const int warp_grid = (N_NODES * 32 + 255) / 256;       // 12500

    // --- layer 0: in_feature[N,1433] @ W0[1433,128] ---
    gemm_tc_k<F_HID><<<gemm_grid, 256>>>(in_feature, W0, g_support_p, N_NODES, F_IN);
    spmm_relu_k<F_HID><<<warp_grid, 256>>>(b0);
    zero_colsum_k<<<1, 128>>>();
    colsum_k<F_HID><<<512, F_HID>>>();
    pairnorm_k<F_HID><<<warp_grid, 256>>>();

    // --- layer 1: g_x[N,128] @ W1[128,128] ---
    gemm_tc_k<F_HID><<<gemm_grid, 256>>>(g_x_p, W1, g_support_p, N_NODES, F_HID);
    spmm_relu_k<F_HID><<<warp_grid, 256>>>(b1);
    zero_colsum_k<<<1, 128>>>();
    colsum_k<F_HID><<<512, F_HID>>>();
    pairnorm_k<F_HID><<<warp_grid, 256>>>();

    // --- layer 2: g_x[N,128] @ W2[128,64] ---
    gemm_tc_k<F_OUT><<<gemm_grid, 256>>>(g_x_p, W2, g_support_p, N_NODES, F_HID);
    spmm_relu_k<F_OUT><<<warp_grid, 256>>>(b2);
    zero_colsum_k<<<1, 128>>>();
    colsum_k<F_OUT><<<512, F_OUT>>>();
    pairnorm_k<F_OUT><<<warp_grid, 256>>>();

    // --- decode ---
    decode_k<<<(N_EDGES * 32 + 255) / 256, 256>>>(pos_ei, neg_ei, out);
}

// round 14
// speedup vs baseline: 1.6685x; 1.3099x over previous
#include <cuda_runtime.h>
#include <cuda_bf16.h>
#include <mma.h>
#include <math.h>
#include <cstdint>

using namespace nvcuda;

#define N_NODES 100000
#define M_PAD   100096
#define N_NNZ   1000000
#define F_IN    1433
#define F_HID   128
#define F_OUT   64
#define N_POS   20000
#define N_NEG   20000
#define N_EDGES (N_POS + N_NEG)
#define EPS     1e-6f
#define T16_L0  90                 // ceil(1433/16)

// ---------------- scratch (static __device__, no allocation) ----------------
__device__ float g_x[(size_t)M_PAD * F_HID];
__device__ float g_support[(size_t)M_PAD * F_HID];
__device__ float g_h[(size_t)N_NODES * F_HID];
__device__ int   g_rowptr[N_NODES + 1];
__device__ int   g_cnt[N_NODES];
__device__ int   g_bsum[128];
__device__ int   g_col[N_NNZ];
__device__ float g_val[N_NNZ];
__device__ float g_colsum[F_HID];
// pre-split weights, BK=16 chunks, pairs packed along n:
// index = t*(16*NT/2) + k*(NT/2) + nh  ->  (W[t*16+k][2nh], W[t*16+k][2nh+1])
__device__ __nv_bfloat162 g_Bth[(size_t)T16_L0 * 16 * (F_HID / 2)];
__device__ __nv_bfloat162 g_Btl[(size_t)T16_L0 * 16 * (F_HID / 2)];

#define SCAN_NB ((N_NODES + 1023) / 1024)

// ---------------- CSR build ----------------
__global__ void zero_cnt_k() {
    int i = blockIdx.x * blockDim.x + threadIdx.x;
    if (i < N_NODES) g_cnt[i] = 0;
}
__global__ void hist_k(const int* __restrict__ row) {
    int i = blockIdx.x * blockDim.x + threadIdx.x;
    if (i < N_NNZ) atomicAdd(&g_cnt[row[i]], 1);
}
__global__ void scanA_k() {
    __shared__ int sm[1024];
    int t = threadIdx.x;
    int i = blockIdx.x * 1024 + t;
    int v = (i < N_NODES) ? g_cnt[i] : 0;
    sm[t] = v;
    __syncthreads();
#pragma unroll
    for (int off = 1; off < 1024; off <<= 1) {
        int add = (t >= off) ? sm[t - off] : 0;
        __syncthreads();
        sm[t] += add;
        __syncthreads();
    }
    if (i < N_NODES) g_rowptr[i] = sm[t] - v;
    if (t == 1023) g_bsum[blockIdx.x] = sm[1023];
}
__global__ void scanB_k() {
    if (threadIdx.x == 0) {
        int run = 0;
        for (int b = 0; b < SCAN_NB; b++) { int v = g_bsum[b]; g_bsum[b] = run; run += v; }
    }
}
__global__ void scanC_k() {
    int i = blockIdx.x * 1024 + threadIdx.x;
    if (i < N_NODES) {
        int v = g_rowptr[i] + g_bsum[blockIdx.x];
        g_rowptr[i] = v;
        g_cnt[i] = v;
    }
    if (i == 0) g_rowptr[N_NODES] = N_NNZ;
}
__global__ void scatter_k(const int* __restrict__ row, const int* __restrict__ col,
                          const float* __restrict__ val) {
    int i = blockIdx.x * blockDim.x + threadIdx.x;
    if (i < N_NNZ) {
        int r = row[i];
        int p = atomicAdd(&g_cnt[r], 1);
        g_col[p] = col[i];
        g_val[p] = val[i];
    }
}

// ---------------- weight pre-split: W[K,NT] -> BK=16 hi/lo pair tiles ---------
__global__ void bsplit_k(const float* __restrict__ W, int K, int NT, int T16) {
    int i = blockIdx.x * blockDim.x + threadIdx.x;
    int hw = NT >> 1;
    int total = T16 * 16 * hw;
    if (i >= total) return;
    int nh = i % hw;
    int rest = i / hw;
    int k = rest & 15;
    int t = rest >> 4;
    int gk = t * 16 + k;
    float v0 = 0.f, v1 = 0.f;
    if (gk < K) {
        v0 = W[(size_t)gk * NT + 2 * nh];
        v1 = W[(size_t)gk * NT + 2 * nh + 1];
    }
    __nv_bfloat16 h0 = __float2bfloat16(v0);
    __nv_bfloat16 h1 = __float2bfloat16(v1);
    __nv_bfloat162 hh; hh.x = h0; hh.y = h1;
    __nv_bfloat162 ll;
    ll.x = __float2bfloat16(v0 - __bfloat162float(h0));
    ll.y = __float2bfloat16(v1 - __bfloat162float(h1));
    g_Bth[i] = hh;
    g_Btl[i] = ll;
}

// ---------------- pipelined bf16-split WMMA GEMM ----------------
// C[M_PAD,NT] = A[M,K] @ W (pre-split global hi/lo tiles)
// Block: 128 rows x NT cols, 256 threads (8 warps: 4 row-groups x 2 col-groups).
// 2-stage software pipeline: register prefetch (t+2) | SMEM convert/store (t+1)
// overlap with MMAs of chunk t; double-buffered SMEM; one sync per iter.
template <int NT>
__global__ __launch_bounds__(256)
void gemm_wm_k(const float* __restrict__ A, float* __restrict__ C, int M, int K, int T) {
    constexpr int LDA = 24;            // 16 + 8 pad (48B rows)
    constexpr int LDB = NT + 8;
    constexpr int WN  = NT / 2;        // warp col width
    constexpr int NF  = WN / 16;       // b-frags per warp
    constexpr int BPF = NT / 32;       // B pairs per thread per buffer (4 or 2)
    constexpr int HW  = NT / 2;

    __shared__ __nv_bfloat16 Ah[2][128][LDA], Al[2][128][LDA];
    __shared__ __nv_bfloat16 Bh[2][16][LDB], Bl[2][16][LDB];

    int tid  = threadIdx.x;
    int warp = tid >> 5;
    int wr   = warp & 3;
    int wc   = warp >> 2;
    int row0 = blockIdx.x * 128;

    wmma::fragment<wmma::accumulator, 16, 16, 16, float> acc[2][NF];
#pragma unroll
    for (int i = 0; i < 2; i++)
#pragma unroll
        for (int j = 0; j < NF; j++) wmma::fill_fragment(acc[i][j], 0.f);

    // prefetch registers
    float a0[4], a1[4];
    uint32_t bhr[BPF], blr[BPF];
    const uint32_t* bth = (const uint32_t*)g_Bth;
    const uint32_t* btl = (const uint32_t*)g_Btl;

    // ---- helpers as lambdas ----
    auto load_regs = [&](int t) {
        int k0 = t * 16;
#pragma unroll
        for (int j = 0; j < 4; j++) {
            int i = tid + j * 256;           // 0..1023 A pairs
            int r = i >> 3, p = i & 7;
            int gr = row0 + r, gk = k0 + 2 * p;
            bool ok = (gr < M);
            a0[j] = (ok && gk < K)     ? __ldg(&A[(size_t)gr * K + gk])     : 0.f;
            a1[j] = (ok && gk + 1 < K) ? __ldg(&A[(size_t)gr * K + gk + 1]) : 0.f;
        }
        const uint32_t* bh = bth + (size_t)t * 16 * HW;
        const uint32_t* bl = btl + (size_t)t * 16 * HW;
#pragma unroll
        for (int j = 0; j < BPF; j++) {
            int i = tid + j * 256;
            bhr[j] = __ldg(&bh[i]);
            blr[j] = __ldg(&bl[i]);
        }
    };
    auto store_smem = [&](int buf) {
#pragma unroll
        for (int j = 0; j < 4; j++) {
            int i = tid + j * 256;
            int r = i >> 3, p = i & 7;
            float x = a0[j], y = a1[j];
            __nv_bfloat16 hx = __float2bfloat16(x), hy = __float2bfloat16(y);
            __nv_bfloat162 hh; hh.x = hx; hh.y = hy;
            __nv_bfloat162 ll;
            ll.x = __float2bfloat16(x - __bfloat162float(hx));
            ll.y = __float2bfloat16(y - __bfloat162float(hy));
            *(__nv_bfloat162*)&Ah[buf][r][2 * p] = hh;
            *(__nv_bfloat162*)&Al[buf][r][2 * p] = ll;
        }
#pragma unroll
        for (int j = 0; j < BPF; j++) {
            int i = tid + j * 256;
            int nh = i % HW, k = i / HW;
            *(uint32_t*)&Bh[buf][k][2 * nh] = bhr[j];
            *(uint32_t*)&Bl[buf][k][2 * nh] = blr[j];
        }
    };

    // ---- prologue ----
    load_regs(0);
    store_smem(0);
    __syncthreads();
    if (T > 1) load_regs(1);

    // ---- main loop ----
    for (int t = 0; t < T; t++) {
        int pb = t & 1;

        wmma::fragment<wmma::matrix_a, 16, 16, 16, __nv_bfloat16, wmma::row_major> afh[2], afl[2];
        wmma::fragment<wmma::matrix_b, 16, 16, 16, __nv_bfloat16, wmma::row_major> bfh[NF], bfl[NF];
#pragma unroll
        for (int i = 0; i < 2; i++) {
            int r = wr * 32 + i * 16;
            wmma::load_matrix_sync(afh[i], &Ah[pb][r][0], LDA);
            wmma::load_matrix_sync(afl[i], &Al[pb][r][0], LDA);
        }
#pragma unroll
        for (int j = 0; j < NF; j++) {
            int c = wc * WN + j * 16;
            wmma::load_matrix_sync(bfh[j], &Bh[pb][0][c], LDB);
            wmma::load_matrix_sync(bfl[j], &Bl[pb][0][c], LDB);
        }
#pragma unroll
        for (int i = 0; i < 2; i++)
#pragma unroll
            for (int j = 0; j < NF; j++) {
                wmma::mma_sync(acc[i][j], afl[i], bfh[j], acc[i][j]);
                wmma::mma_sync(acc[i][j], afh[i], bfl[j], acc[i][j]);
                wmma::mma_sync(acc[i][j], afh[i], bfh[j], acc[i][j]);
            }

        if (t + 1 < T) store_smem((t + 1) & 1);
        __syncthreads();
        if (t + 2 < T) load_regs(t + 2);
    }

    // ---- epilogue (C padded to M_PAD rows: no guard) ----
#pragma unroll
    for (int i = 0; i < 2; i++)
#pragma unroll
        for (int j = 0; j < NF; j++) {
            int r = row0 + wr * 32 + i * 16;
            int c = wc * WN + j * 16;
            wmma::store_matrix_sync(&C[(size_t)r * NT + c], acc[i][j], NT, wmma::mem_row_major);
        }
}

// ---------------- SpMM (CSR) + bias + ReLU : one warp per row ----------------
template <int F>
__global__ void spmm_relu_k(const float* __restrict__ bias) {
    constexpr int VEC = F / 32;
    int w = (blockIdx.x * blockDim.x + threadIdx.x) >> 5;
    if (w >= N_NODES) return;
    int lane = threadIdx.x & 31;

    float acc[VEC];
#pragma unroll
    for (int v = 0; v < VEC; v++) acc[v] = 0.f;

    int s = g_rowptr[w], e = g_rowptr[w + 1];
    const float* base = g_support;
    for (int j = s; j < e; j++) {
        int c = __ldg(&g_col[j]);
        float vv = __ldg(&g_val[j]);
        const float* p = base + (size_t)c * F + lane * VEC;
        if (VEC == 4) {
            float4 q = *reinterpret_cast<const float4*>(p);
            acc[0] += vv * q.x; acc[1] += vv * q.y;
            acc[2] += vv * q.z; acc[3] += vv * q.w;
        } else {
            float2 q = *reinterpret_cast<const float2*>(p);
            acc[0] += vv * q.x; acc[1] += vv * q.y;
        }
    }

    float* out = g_h + (size_t)w * F + lane * VEC;
    if (VEC == 4) {
        float4 b = *reinterpret_cast<const float4*>(bias + lane * 4);
        float4 r;
        r.x = fmaxf(acc[0] + b.x, 0.f);
        r.y = fmaxf(acc[1] + b.y, 0.f);
        r.z = fmaxf(acc[2] + b.z, 0.f);
        r.w = fmaxf(acc[3] + b.w, 0.f);
        *reinterpret_cast<float4*>(out) = r;
    } else {
        float2 b = *reinterpret_cast<const float2*>(bias + lane * 2);
        float2 r;
        r.x = fmaxf(acc[0] + b.x, 0.f);
        r.y = fmaxf(acc[1] + b.y, 0.f);
        *reinterpret_cast<float2*>(out) = r;
    }
}

// ---------------- column sums ----------------
__global__ void zero_colsum_k() {
    if (threadIdx.x < F_HID) g_colsum[threadIdx.x] = 0.f;
}
template <int F>
__global__ void colsum_k() {
    int f = threadIdx.x;
    float s = 0.f;
    for (int r = blockIdx.x; r < N_NODES; r += gridDim.x)
        s += g_h[(size_t)r * F + f];
    atomicAdd(&g_colsum[f], s);
}

// ---------------- PairNorm (PN-SI) ----------------
template <int F>
__global__ void pairnorm_k() {
    constexpr int VEC = F / 32;
    int w = (blockIdx.x * blockDim.x + threadIdx.x) >> 5;
    if (w >= N_NODES) return;
    int lane = threadIdx.x & 31;

    float v[VEC];
    const float* src = g_h + (size_t)w * F + lane * VEC;
    if (VEC == 4) {
        float4 q = *reinterpret_cast<const float4*>(src);
        v[0] = q.x; v[1] = q.y; v[2] = q.z; v[3] = q.w;
    } else {
        float2 q = *reinterpret_cast<const float2*>(src);
        v[0] = q.x; v[1] = q.y;
    }
    const float invN = 1.0f / (float)N_NODES;
    float ss = 0.f;
#pragma unroll
    for (int i = 0; i < VEC; i++) {
        float m = g_colsum[lane * VEC + i] * invN;
        v[i] -= m;
        ss += v[i] * v[i];
    }
#pragma unroll
    for (int off = 16; off > 0; off >>= 1)
        ss += __shfl_xor_sync(0xFFFFFFFFu, ss, off);
    float inv = 1.0f / sqrtf(EPS + ss);

    float* dst = g_x + (size_t)w * F + lane * VEC;
    if (VEC == 4) {
        float4 r; r.x = v[0] * inv; r.y = v[1] * inv; r.z = v[2] * inv; r.w = v[3] * inv;
        *reinterpret_cast<float4*>(dst) = r;
    } else {
        float2 r; r.x = v[0] * inv; r.y = v[1] * inv;
        *reinterpret_cast<float2*>(dst) = r;
    }
}

// ---------------- decode ----------------
__global__ void decode_k(const int* __restrict__ pos, const int* __restrict__ neg,
                         float* __restrict__ out) {
    int w = (blockIdx.x * blockDim.x + threadIdx.x) >> 5;
    if (w >= N_EDGES) return;
    int lane = threadIdx.x & 31;
    int s, d;
    if (w < N_POS) { s = pos[2 * w]; d = pos[2 * w + 1]; }
    else { int e = w - N_POS; s = neg[2 * e]; d = neg[2 * e + 1]; }
    float2 a = *reinterpret_cast<const float2*>(g_x + (size_t)s * F_OUT + lane * 2);
    float2 b = *reinterpret_cast<const float2*>(g_x + (size_t)d * F_OUT + lane * 2);
    float p = a.x * b.x + a.y * b.y;
#pragma unroll
    for (int off = 16; off > 0; off >>= 1)
        p += __shfl_xor_sync(0xFFFFFFFFu, p, off);
    if (lane == 0) out[w] = 1.0f / (1.0f + expf(-p));
}

// ---------------- launch ----------------
extern "C" void kernel_launch(void* const* d_in, const int* in_sizes, int n_in,
                              void* d_out, int out_size) {
    const float* in_feature = (const float*)d_in[0];
    const int*   adj_row    = (const int*)d_in[1];
    const int*   adj_col    = (const int*)d_in[2];
    const float* adj_val    = (const float*)d_in[3];
    const int*   pos_ei     = (const int*)d_in[4];
    const int*   neg_ei     = (const int*)d_in[5];
    const float* W0 = (const float*)d_in[6];
    const float* b0 = (const float*)d_in[7];
    const float* W1 = (const float*)d_in[8];
    const float* b1 = (const float*)d_in[9];
    const float* W2 = (const float*)d_in[10];
    const float* b2 = (const float*)d_in[11];
    float* out = (float*)d_out;

    float *g_x_p, *g_support_p;
    cudaGetSymbolAddress((void**)&g_x_p, g_x);
    cudaGetSymbolAddress((void**)&g_support_p, g_support);

    const int gemm_grid = (N_NODES + 127) / 128;            // 782
    const int warp_grid = (N_NODES * 32 + 255) / 256;       // 12500

    // launch order chosen so the big L0 GEMM sits in ncu's -s/-c capture window
    bsplit_k<<<(T16_L0 * 16 * (F_HID / 2) + 255) / 256, 256>>>(W0, F_IN, F_HID, T16_L0);   // 1
    zero_cnt_k<<<(N_NODES + 255) / 256, 256>>>();                                           // 2
    hist_k<<<(N_NNZ + 255) / 256, 256>>>(adj_row);                                          // 3
    gemm_wm_k<F_HID><<<gemm_grid, 256>>>(in_feature, g_support_p, N_NODES, F_IN, T16_L0);   // 4 (BIG)
    scanA_k<<<SCAN_NB, 1024>>>();                                                           // 5
    scanB_k<<<1, 32>>>();                                                                   // 6
    scanC_k<<<SCAN_NB, 1024>>>();                                                           // 7
    scatter_k<<<(N_NNZ + 255) / 256, 256>>>(adj_row, adj_col, adj_val);                     // 8

    // --- layer 0 tail ---
    spmm_relu_k<F_HID><<<warp_grid, 256>>>(b0);
    zero_colsum_k<<<1, 128>>>();
    colsum_k<F_HID><<<512, F_HID>>>();
    pairnorm_k<F_HID><<<warp_grid, 256>>>();

    // --- layer 1: g_x[N,128] @ W1[128,128] ---
    bsplit_k<<<(8 * 16 * (F_HID / 2) + 255) / 256, 256>>>(W1, F_HID, F_HID, 8);
    gemm_wm_k<F_HID><<<gemm_grid, 256>>>(g_x_p, g_support_p, N_NODES, F_HID, 8);
    spmm_relu_k<F_HID><<<warp_grid, 256>>>(b1);
    zero_colsum_k<<<1, 128>>>();
    colsum_k<F_HID><<<512, F_HID>>>();
    pairnorm_k<F_HID><<<warp_grid, 256>>>();

    // --- layer 2: g_x[N,128] @ W2[128,64] ---
    bsplit_k<<<(8 * 16 * (F_OUT / 2) + 255) / 256, 256>>>(W2, F_HID, F_OUT, 8);
    gemm_wm_k<F_OUT><<<gemm_grid, 256>>>(g_x_p, g_support_p, N_NODES, F_HID, 8);
    spmm_relu_k<F_OUT><<<warp_grid, 256>>>(b2);
    zero_colsum_k<<<1, 128>>>();
    colsum_k<F_OUT><<<512, F_OUT>>>();
    pairnorm_k<F_OUT><<<warp_grid, 256>>>();

    // --- decode ---
    decode_k<<<(N_EDGES * 32 + 255) / 256, 256>>>(pos_ei, neg_ei, out);
}

// round 15
// speedup vs baseline: 1.7067x; 1.0229x over previous
#include <cuda_runtime.h>
#include <cuda_bf16.h>
#include <mma.h>
#include <math.h>
#include <cstdint>

using namespace nvcuda;

#define N_NODES 100000
#define M_PAD   100096
#define N_NNZ   1000000
#define F_IN    1433
#define F_HID   128
#define F_OUT   64
#define N_POS   20000
#define N_NEG   20000
#define N_EDGES (N_POS + N_NEG)
#define EPS     1e-6f
#define T16_L0  90                 // ceil(1433/16)

// ---------------- scratch (static __device__, no allocation) ----------------
__device__ float g_x[(size_t)M_PAD * F_HID];
__device__ float g_support[(size_t)M_PAD * F_HID];
__device__ float g_h[(size_t)N_NODES * F_HID];
__device__ int   g_rowptr[N_NODES + 1];
__device__ int   g_cnt[N_NODES];
__device__ int   g_bsum[128];
__device__ int   g_col[N_NNZ];
__device__ float g_val[N_NNZ];
__device__ float g_colsum[F_HID];
// pre-split weights, BK=16 chunks, pairs packed along n:
// index = t*(16*NT/2) + k*(NT/2) + nh  ->  (W[t*16+k][2nh], W[t*16+k][2nh+1])
__device__ __nv_bfloat162 g_Bth[(size_t)T16_L0 * 16 * (F_HID / 2)];
__device__ __nv_bfloat162 g_Btl[(size_t)T16_L0 * 16 * (F_HID / 2)];

#define SCAN_NB ((N_NODES + 1023) / 1024)

// ---------------- CSR build ----------------
__global__ void zero_cnt_k() {
    int i = blockIdx.x * blockDim.x + threadIdx.x;
    if (i < N_NODES) g_cnt[i] = 0;
}
__global__ void hist_k(const int* __restrict__ row) {
    int i = blockIdx.x * blockDim.x + threadIdx.x;
    if (i < N_NNZ) atomicAdd(&g_cnt[row[i]], 1);
}
__global__ void scanA_k() {
    __shared__ int sm[1024];
    int t = threadIdx.x;
    int i = blockIdx.x * 1024 + t;
    int v = (i < N_NODES) ? g_cnt[i] : 0;
    sm[t] = v;
    __syncthreads();
#pragma unroll
    for (int off = 1; off < 1024; off <<= 1) {
        int add = (t >= off) ? sm[t - off] : 0;
        __syncthreads();
        sm[t] += add;
        __syncthreads();
    }
    if (i < N_NODES) g_rowptr[i] = sm[t] - v;
    if (t == 1023) g_bsum[blockIdx.x] = sm[1023];
}
__global__ void scanB_k() {
    if (threadIdx.x == 0) {
        int run = 0;
        for (int b = 0; b < SCAN_NB; b++) { int v = g_bsum[b]; g_bsum[b] = run; run += v; }
    }
}
__global__ void scanC_k() {
    int i = blockIdx.x * 1024 + threadIdx.x;
    if (i < N_NODES) {
        int v = g_rowptr[i] + g_bsum[blockIdx.x];
        g_rowptr[i] = v;
        g_cnt[i] = v;
    }
    if (i == 0) g_rowptr[N_NODES] = N_NNZ;
}
__global__ void scatter_k(const int* __restrict__ row, const int* __restrict__ col,
                          const float* __restrict__ val) {
    int i = blockIdx.x * blockDim.x + threadIdx.x;
    if (i < N_NNZ) {
        int r = row[i];
        int p = atomicAdd(&g_cnt[r], 1);
        g_col[p] = col[i];
        g_val[p] = val[i];
    }
}

// ---------------- weight pre-split: W[K,NT] -> BK=16 hi/lo pair tiles ---------
__global__ void bsplit_k(const float* __restrict__ W, int K, int NT, int T16) {
    int i = blockIdx.x * blockDim.x + threadIdx.x;
    int hw = NT >> 1;
    int total = T16 * 16 * hw;
    if (i >= total) return;
    int nh = i % hw;
    int rest = i / hw;
    int k = rest & 15;
    int t = rest >> 4;
    int gk = t * 16 + k;
    float v0 = 0.f, v1 = 0.f;
    if (gk < K) {
        v0 = W[(size_t)gk * NT + 2 * nh];
        v1 = W[(size_t)gk * NT + 2 * nh + 1];
    }
    __nv_bfloat16 h0 = __float2bfloat16(v0);
    __nv_bfloat16 h1 = __float2bfloat16(v1);
    __nv_bfloat162 hh; hh.x = h0; hh.y = h1;
    __nv_bfloat162 ll;
    ll.x = __float2bfloat16(v0 - __bfloat162float(h0));
    ll.y = __float2bfloat16(v1 - __bfloat162float(h1));
    g_Bth[i] = hh;
    g_Btl[i] = ll;
}

// ---------------- pipelined bf16-split WMMA GEMM (2 blocks/SM) ----------------
// C[M_PAD,NT] = A[M,K] @ W (pre-split global hi/lo tiles)
// Block: 128 rows x NT cols, 256 threads (8 warps: 4 row-groups x 2 col-groups).
// 2-stage software pipeline as before. Register budget engineered for 128 regs
// (=> 2 co-resident blocks/SM): B fragments loaded one column-group at a time.
template <int NT>
__global__ __launch_bounds__(256, 2)
void gemm_wm_k(const float* __restrict__ A, float* __restrict__ C, int M, int K, int T) {
    constexpr int LDA = 24;            // 16 + 8 pad (48B rows)
    constexpr int LDB = NT + 8;
    constexpr int WN  = NT / 2;        // warp col width
    constexpr int NF  = WN / 16;       // b-frags per warp
    constexpr int BPF = NT / 32;       // B pairs per thread per buffer (4 or 2)
    constexpr int HW  = NT / 2;

    __shared__ __nv_bfloat16 Ah[2][128][LDA], Al[2][128][LDA];
    __shared__ __nv_bfloat16 Bh[2][16][LDB], Bl[2][16][LDB];

    int tid  = threadIdx.x;
    int warp = tid >> 5;
    int wr   = warp & 3;
    int wc   = warp >> 2;
    int row0 = blockIdx.x * 128;

    wmma::fragment<wmma::accumulator, 16, 16, 16, float> acc[2][NF];
#pragma unroll
    for (int i = 0; i < 2; i++)
#pragma unroll
        for (int j = 0; j < NF; j++) wmma::fill_fragment(acc[i][j], 0.f);

    // prefetch registers
    float a0[4], a1[4];
    uint32_t bhr[BPF], blr[BPF];
    const uint32_t* bth = (const uint32_t*)g_Bth;
    const uint32_t* btl = (const uint32_t*)g_Btl;

    auto load_regs = [&](int t) {
        int k0 = t * 16;
#pragma unroll
        for (int j = 0; j < 4; j++) {
            int i = tid + j * 256;           // 0..1023 A pairs
            int r = i >> 3, p = i & 7;
            int gr = row0 + r, gk = k0 + 2 * p;
            bool ok = (gr < M);
            a0[j] = (ok && gk < K)     ? __ldg(&A[(size_t)gr * K + gk])     : 0.f;
            a1[j] = (ok && gk + 1 < K) ? __ldg(&A[(size_t)gr * K + gk + 1]) : 0.f;
        }
        const uint32_t* bh = bth + (size_t)t * 16 * HW;
        const uint32_t* bl = btl + (size_t)t * 16 * HW;
#pragma unroll
        for (int j = 0; j < BPF; j++) {
            int i = tid + j * 256;
            bhr[j] = __ldg(&bh[i]);
            blr[j] = __ldg(&bl[i]);
        }
    };
    auto store_smem = [&](int buf) {
#pragma unroll
        for (int j = 0; j < 4; j++) {
            int i = tid + j * 256;
            int r = i >> 3, p = i & 7;
            float x = a0[j], y = a1[j];
            __nv_bfloat16 hx = __float2bfloat16(x), hy = __float2bfloat16(y);
            __nv_bfloat162 hh; hh.x = hx; hh.y = hy;
            __nv_bfloat162 ll;
            ll.x = __float2bfloat16(x - __bfloat162float(hx));
            ll.y = __float2bfloat16(y - __bfloat162float(hy));
            *(__nv_bfloat162*)&Ah[buf][r][2 * p] = hh;
            *(__nv_bfloat162*)&Al[buf][r][2 * p] = ll;
        }
#pragma unroll
        for (int j = 0; j < BPF; j++) {
            int i = tid + j * 256;
            int nh = i % HW, k = i / HW;
            *(uint32_t*)&Bh[buf][k][2 * nh] = bhr[j];
            *(uint32_t*)&Bl[buf][k][2 * nh] = blr[j];
        }
    };

    // ---- prologue ----
    load_regs(0);
    store_smem(0);
    __syncthreads();
    if (T > 1) load_regs(1);

    // ---- main loop ----
    for (int t = 0; t < T; t++) {
        int pb = t & 1;

        // A fragments stay resident (16 regs); B fragments loaded per column
        // group (8 regs live) to keep total regs under the 128 cap.
        wmma::fragment<wmma::matrix_a, 16, 16, 16, __nv_bfloat16, wmma::row_major> afh[2], afl[2];
#pragma unroll
        for (int i = 0; i < 2; i++) {
            int r = wr * 32 + i * 16;
            wmma::load_matrix_sync(afh[i], &Ah[pb][r][0], LDA);
            wmma::load_matrix_sync(afl[i], &Al[pb][r][0], LDA);
        }
#pragma unroll
        for (int j = 0; j < NF; j++) {
            wmma::fragment<wmma::matrix_b, 16, 16, 16, __nv_bfloat16, wmma::row_major> bfh, bfl;
            int c = wc * WN + j * 16;
            wmma::load_matrix_sync(bfh, &Bh[pb][0][c], LDB);
            wmma::load_matrix_sync(bfl, &Bl[pb][0][c], LDB);
#pragma unroll
            for (int i = 0; i < 2; i++) {
                wmma::mma_sync(acc[i][j], afl[i], bfh, acc[i][j]);
                wmma::mma_sync(acc[i][j], afh[i], bfl, acc[i][j]);
                wmma::mma_sync(acc[i][j], afh[i], bfh, acc[i][j]);
            }
        }

        if (t + 1 < T) store_smem((t + 1) & 1);
        __syncthreads();
        if (t + 2 < T) load_regs(t + 2);
    }

    // ---- epilogue (C padded to M_PAD rows: no guard) ----
#pragma unroll
    for (int i = 0; i < 2; i++)
#pragma unroll
        for (int j = 0; j < NF; j++) {
            int r = row0 + wr * 32 + i * 16;
            int c = wc * WN + j * 16;
            wmma::store_matrix_sync(&C[(size_t)r * NT + c], acc[i][j], NT, wmma::mem_row_major);
        }
}

// ---------------- SpMM (CSR) + bias + ReLU : one warp per row ----------------
template <int F>
__global__ void spmm_relu_k(const float* __restrict__ bias) {
    constexpr int VEC = F / 32;
    int w = (blockIdx.x * blockDim.x + threadIdx.x) >> 5;
    if (w >= N_NODES) return;
    int lane = threadIdx.x & 31;

    float acc[VEC];
#pragma unroll
    for (int v = 0; v < VEC; v++) acc[v] = 0.f;

    int s = g_rowptr[w], e = g_rowptr[w + 1];
    const float* base = g_support;
    for (int j = s; j < e; j++) {
        int c = __ldg(&g_col[j]);
        float vv = __ldg(&g_val[j]);
        const float* p = base + (size_t)c * F + lane * VEC;
        if (VEC == 4) {
            float4 q = *reinterpret_cast<const float4*>(p);
            acc[0] += vv * q.x; acc[1] += vv * q.y;
            acc[2] += vv * q.z; acc[3] += vv * q.w;
        } else {
            float2 q = *reinterpret_cast<const float2*>(p);
            acc[0] += vv * q.x; acc[1] += vv * q.y;
        }
    }

    float* out = g_h + (size_t)w * F + lane * VEC;
    if (VEC == 4) {
        float4 b = *reinterpret_cast<const float4*>(bias + lane * 4);
        float4 r;
        r.x = fmaxf(acc[0] + b.x, 0.f);
        r.y = fmaxf(acc[1] + b.y, 0.f);
        r.z = fmaxf(acc[2] + b.z, 0.f);
        r.w = fmaxf(acc[3] + b.w, 0.f);
        *reinterpret_cast<float4*>(out) = r;
    } else {
        float2 b = *reinterpret_cast<const float2*>(bias + lane * 2);
        float2 r;
        r.x = fmaxf(acc[0] + b.x, 0.f);
        r.y = fmaxf(acc[1] + b.y, 0.f);
        *reinterpret_cast<float2*>(out) = r;
    }
}

// ---------------- column sums ----------------
__global__ void zero_colsum_k() {
    if (threadIdx.x < F_HID) g_colsum[threadIdx.x] = 0.f;
}
template <int F>
__global__ void colsum_k() {
    int f = threadIdx.x;
    float s = 0.f;
    for (int r = blockIdx.x; r < N_NODES; r += gridDim.x)
        s += g_h[(size_t)r * F + f];
    atomicAdd(&g_colsum[f], s);
}

// ---------------- PairNorm (PN-SI) ----------------
template <int F>
__global__ void pairnorm_k() {
    constexpr int VEC = F / 32;
    int w = (blockIdx.x * blockDim.x + threadIdx.x) >> 5;
    if (w >= N_NODES) return;
    int lane = threadIdx.x & 31;

    float v[VEC];
    const float* src = g_h + (size_t)w * F + lane * VEC;
    if (VEC == 4) {
        float4 q = *reinterpret_cast<const float4*>(src);
        v[0] = q.x; v[1] = q.y; v[2] = q.z; v[3] = q.w;
    } else {
        float2 q = *reinterpret_cast<const float2*>(src);
        v[0] = q.x; v[1] = q.y;
    }
    const float invN = 1.0f / (float)N_NODES;
    float ss = 0.f;
#pragma unroll
    for (int i = 0; i < VEC; i++) {
        float m = g_colsum[lane * VEC + i] * invN;
        v[i] -= m;
        ss += v[i] * v[i];
    }
#pragma unroll
    for (int off = 16; off > 0; off >>= 1)
        ss += __shfl_xor_sync(0xFFFFFFFFu, ss, off);
    float inv = 1.0f / sqrtf(EPS + ss);

    float* dst = g_x + (size_t)w * F + lane * VEC;
    if (VEC == 4) {
        float4 r; r.x = v[0] * inv; r.y = v[1] * inv; r.z = v[2] * inv; r.w = v[3] * inv;
        *reinterpret_cast<float4*>(dst) = r;
    } else {
        float2 r; r.x = v[0] * inv; r.y = v[1] * inv;
        *reinterpret_cast<float2*>(dst) = r;
    }
}

// ---------------- decode ----------------
__global__ void decode_k(const int* __restrict__ pos, const int* __restrict__ neg,
                         float* __restrict__ out) {
    int w = (blockIdx.x * blockDim.x + threadIdx.x) >> 5;
    if (w >= N_EDGES) return;
    int lane = threadIdx.x & 31;
    int s, d;
    if (w < N_POS) { s = pos[2 * w]; d = pos[2 * w + 1]; }
    else { int e = w - N_POS; s = neg[2 * e]; d = neg[2 * e + 1]; }
    float2 a = *reinterpret_cast<const float2*>(g_x + (size_t)s * F_OUT + lane * 2);
    float2 b = *reinterpret_cast<const float2*>(g_x + (size_t)d * F_OUT + lane * 2);
    float p = a.x * b.x + a.y * b.y;
#pragma unroll
    for (int off = 16; off > 0; off >>= 1)
        p += __shfl_xor_sync(0xFFFFFFFFu, p, off);
    if (lane == 0) out[w] = 1.0f / (1.0f + expf(-p));
}

// ---------------- launch ----------------
extern "C" void kernel_launch(void* const* d_in, const int* in_sizes, int n_in,
                              void* d_out, int out_size) {
    const float* in_feature = (const float*)d_in[0];
    const int*   adj_row    = (const int*)d_in[1];
    const int*   adj_col    = (const int*)d_in[2];
    const float* adj_val    = (const float*)d_in[3];
    const int*   pos_ei     = (const int*)d_in[4];
    const int*   neg_ei     = (const int*)d_in[5];
    const float* W0 = (const float*)d_in[6];
    const float* b0 = (const float*)d_in[7];
    const float* W1 = (const float*)d_in[8];
    const float* b1 = (const float*)d_in[9];
    const float* W2 = (const float*)d_in[10];
    const float* b2 = (const float*)d_in[11];
    float* out = (float*)d_out;

    float *g_x_p, *g_support_p;
    cudaGetSymbolAddress((void**)&g_x_p, g_x);
    cudaGetSymbolAddress((void**)&g_support_p, g_support);

    const int gemm_grid = (N_NODES + 127) / 128;            // 782
    const int warp_grid = (N_NODES * 32 + 255) / 256;       // 12500

    // launch order chosen so the big L0 GEMM sits in ncu's -s/-c capture window
    bsplit_k<<<(T16_L0 * 16 * (F_HID / 2) + 255) / 256, 256>>>(W0, F_IN, F_HID, T16_L0);   // 1
    zero_cnt_k<<<(N_NODES + 255) / 256, 256>>>();                                           // 2
    hist_k<<<(N_NNZ + 255) / 256, 256>>>(adj_row);                                          // 3
    gemm_wm_k<F_HID><<<gemm_grid, 256>>>(in_feature, g_support_p, N_NODES, F_IN, T16_L0);   // 4 (BIG)
    scanA_k<<<SCAN_NB, 1024>>>();                                                           // 5
    scanB_k<<<1, 32>>>();                                                                   // 6
    scanC_k<<<SCAN_NB, 1024>>>();                                                           // 7
    scatter_k<<<(N_NNZ + 255) / 256, 256>>>(adj_row, adj_col, adj_val);                     // 8

    // --- layer 0 tail ---
    spmm_relu_k<F_HID><<<warp_grid, 256>>>(b0);
    zero_colsum_k<<<1, 128>>>();
    colsum_k<F_HID><<<512, F_HID>>>();
    pairnorm_k<F_HID><<<warp_grid, 256>>>();

    // --- layer 1: g_x[N,128] @ W1[128,128] ---
    bsplit_k<<<(8 * 16 * (F_HID / 2) + 255) / 256, 256>>>(W1, F_HID, F_HID, 8);
    gemm_wm_k<F_HID><<<gemm_grid, 256>>>(g_x_p, g_support_p, N_NODES, F_HID, 8);
    spmm_relu_k<F_HID><<<warp_grid, 256>>>(b1);
    zero_colsum_k<<<1, 128>>>();
    colsum_k<F_HID><<<512, F_HID>>>();
    pairnorm_k<F_HID><<<warp_grid, 256>>>();

    // --- layer 2: g_x[N,128] @ W2[128,64] ---
    bsplit_k<<<(8 * 16 * (F_OUT / 2) + 255) / 256, 256>>>(W2, F_HID, F_OUT, 8);
    gemm_wm_k<F_OUT><<<gemm_grid, 256>>>(g_x_p, g_support_p, N_NODES, F_HID, 8);
    spmm_relu_k<F_OUT><<<warp_grid, 256>>>(b2);
    zero_colsum_k<<<1, 128>>>();
    colsum_k<F_OUT><<<512, F_OUT>>>();
    pairnorm_k<F_OUT><<<warp_grid, 256>>>();

    // --- decode ---
    decode_k<<<(N_EDGES * 32 + 255) / 256, 256>>>(pos_ei, neg_ei, out);
}

// round 16
// speedup vs baseline: 2.0023x; 1.1732x over previous
#include <cuda_runtime.h>
#include <cuda_bf16.h>
#include <math.h>
#include <cstdint>

#define N_NODES 100000
#define M_PAD   100096
#define N_NNZ   1000000
#define F_IN    1433
#define F_HID   128
#define F_OUT   64
#define N_POS   20000
#define N_NEG   20000
#define N_EDGES (N_POS + N_NEG)
#define EPS     1e-6f
#define T16_L0  90                 // ceil(1433/16)

// ---------------- scratch (static __device__, no allocation) ----------------
__device__ float g_x[(size_t)M_PAD * F_HID];          // zero-init: pad rows stay 0
__device__ float g_support[(size_t)M_PAD * F_HID];
__device__ float g_h[(size_t)N_NODES * F_HID];
__device__ int   g_rowptr[N_NODES + 1];
__device__ int   g_cnt[N_NODES];
__device__ int   g_bsum[128];
__device__ int   g_col[N_NNZ];
__device__ float g_val[N_NNZ];
__device__ float g_colsum[F_HID];
// B fragments pre-packed in exact mma.sync m16n8k16 per-lane layout:
// index = (t*NTILES + jg)*32 + lane  ->  uint2 {reg0, reg1}
__device__ uint2 g_Bfh[(size_t)T16_L0 * 16 * 32];
__device__ uint2 g_Bfl[(size_t)T16_L0 * 16 * 32];

#define SCAN_NB ((N_NODES + 1023) / 1024)

// ---------------- helpers ----------------
__device__ __forceinline__ void split2(float x, float y, uint32_t& hi, uint32_t& lo) {
    __nv_bfloat162 h = __float22bfloat162_rn(make_float2(x, y));
    float rx = x - __bfloat162float(h.x);
    float ry = y - __bfloat162float(h.y);
    __nv_bfloat162 l = __float22bfloat162_rn(make_float2(rx, ry));
    hi = *reinterpret_cast<uint32_t*>(&h);
    lo = *reinterpret_cast<uint32_t*>(&l);
}

__device__ __forceinline__ void mma16816(float* c, const uint32_t* a,
                                         uint32_t b0, uint32_t b1) {
    asm volatile(
        "mma.sync.aligned.m16n8k16.row.col.f32.bf16.bf16.f32 "
        "{%0,%1,%2,%3}, {%4,%5,%6,%7}, {%8,%9}, {%0,%1,%2,%3};\n"
        : "+f"(c[0]), "+f"(c[1]), "+f"(c[2]), "+f"(c[3])
        : "r"(a[0]), "r"(a[1]), "r"(a[2]), "r"(a[3]), "r"(b0), "r"(b1));
}

// ---------------- CSR build ----------------
__global__ void zero_cnt_k() {
    int i = blockIdx.x * blockDim.x + threadIdx.x;
    if (i < N_NODES) g_cnt[i] = 0;
}
__global__ void hist_k(const int* __restrict__ row) {
    int i = blockIdx.x * blockDim.x + threadIdx.x;
    if (i < N_NNZ) atomicAdd(&g_cnt[row[i]], 1);
}
__global__ void scanA_k() {
    __shared__ int sm[1024];
    int t = threadIdx.x;
    int i = blockIdx.x * 1024 + t;
    int v = (i < N_NODES) ? g_cnt[i] : 0;
    sm[t] = v;
    __syncthreads();
#pragma unroll
    for (int off = 1; off < 1024; off <<= 1) {
        int add = (t >= off) ? sm[t - off] : 0;
        __syncthreads();
        sm[t] += add;
        __syncthreads();
    }
    if (i < N_NODES) g_rowptr[i] = sm[t] - v;
    if (t == 1023) g_bsum[blockIdx.x] = sm[1023];
}
__global__ void scanB_k() {
    if (threadIdx.x == 0) {
        int run = 0;
        for (int b = 0; b < SCAN_NB; b++) { int v = g_bsum[b]; g_bsum[b] = run; run += v; }
    }
}
__global__ void scanC_k() {
    int i = blockIdx.x * 1024 + threadIdx.x;
    if (i < N_NODES) {
        int v = g_rowptr[i] + g_bsum[blockIdx.x];
        g_rowptr[i] = v;
        g_cnt[i] = v;
    }
    if (i == 0) g_rowptr[N_NODES] = N_NNZ;
}
__global__ void scatter_k(const int* __restrict__ row, const int* __restrict__ col,
                          const float* __restrict__ val) {
    int i = blockIdx.x * blockDim.x + threadIdx.x;
    if (i < N_NNZ) {
        int r = row[i];
        int p = atomicAdd(&g_cnt[r], 1);
        g_col[p] = col[i];
        g_val[p] = val[i];
    }
}

// -------- weight pre-pack into mma B-fragment register layout, hi/lo split ----
// For chunk t, ntile jg, lane l: n = jg*8 + l/4, k = (l%4)*2 (+1, +8, +9)
__global__ void bsplit2_k(const float* __restrict__ W, int K, int NT, int T16) {
    int i = blockIdx.x * blockDim.x + threadIdx.x;
    int ntiles = NT >> 3;
    int total = T16 * ntiles * 32;
    if (i >= total) return;
    int lane = i & 31;
    int jg   = (i >> 5) % ntiles;
    int t    = i / (32 * ntiles);
    int n    = jg * 8 + (lane >> 2);
    int gk   = t * 16 + (lane & 3) * 2;

    float v0 = (gk     < K) ? W[(size_t)gk * NT + n]       : 0.f;
    float v1 = (gk + 1 < K) ? W[(size_t)(gk + 1) * NT + n] : 0.f;
    float v2 = (gk + 8 < K) ? W[(size_t)(gk + 8) * NT + n] : 0.f;
    float v3 = (gk + 9 < K) ? W[(size_t)(gk + 9) * NT + n] : 0.f;
    uint2 hi, lo;
    split2(v0, v1, hi.x, lo.x);
    split2(v2, v3, hi.y, lo.y);
    g_Bfh[i] = hi;
    g_Bfl[i] = lo;
}

// ---------------- SMEM-free fragment GEMM ----------------
// C[*, NT] = A[*, K] @ W (pre-packed B fragments), 3-pass bf16 split.
// One warp = 32 rows x 64 cols. 128-thread blocks, no shared memory, no syncs.
// NT=128: 2 column halves per row-tile; NT=64: 1.
template <int NT>
__global__ __launch_bounds__(128)
void gemm_frag_k(const float* __restrict__ A, float* __restrict__ C,
                 int K, int T, int totalWarps) {
    constexpr int CH = NT / 64;            // column halves
    constexpr int NTILES = NT / 8;

    int w = blockIdx.x * 4 + (threadIdx.x >> 5);
    if (w >= totalWarps) return;
    int lane = threadIdx.x & 31;
    int rowTile, colHalf;
    if (CH == 2) { rowTile = w >> 1; colHalf = w & 1; }
    else         { rowTile = w;      colHalf = 0;     }
    int rowBase = rowTile * 32;
    int jgBase  = colHalf * 8;

    float acc[2][8][4];
#pragma unroll
    for (int i = 0; i < 2; i++)
#pragma unroll
        for (int j = 0; j < 8; j++)
#pragma unroll
            for (int q = 0; q < 4; q++) acc[i][j][q] = 0.f;

    int lq = lane >> 2;                    // 0..7 row within 8-row group
    int lk = (lane & 3) * 2;               // k pair offset

    for (int t = 0; t < T; t++) {
        int k0 = t * 16;
        uint32_t ah[2][4], al[2][4];
        // ---- build A fragments straight from global fp32 ----
        if (k0 + 15 < K) {
#pragma unroll
            for (int i = 0; i < 2; i++) {
                const float* pa = A + (size_t)(rowBase + i * 16 + lq) * K + k0 + lk;
                const float* pb = pa + (size_t)8 * K;
                split2(pa[0], pa[1], ah[i][0], al[i][0]);
                split2(pb[0], pb[1], ah[i][1], al[i][1]);
                split2(pa[8], pa[9], ah[i][2], al[i][2]);
                split2(pb[8], pb[9], ah[i][3], al[i][3]);
            }
        } else {
#pragma unroll
            for (int i = 0; i < 2; i++) {
                const float* pa = A + (size_t)(rowBase + i * 16 + lq) * K;
                const float* pb = pa + (size_t)8 * K;
                int kc = k0 + lk;
                float v0 = (kc     < K) ? pa[kc]     : 0.f;
                float v1 = (kc + 1 < K) ? pa[kc + 1] : 0.f;
                float v2 = (kc     < K) ? pb[kc]     : 0.f;
                float v3 = (kc + 1 < K) ? pb[kc + 1] : 0.f;
                float v4 = (kc + 8 < K) ? pa[kc + 8] : 0.f;
                float v5 = (kc + 9 < K) ? pa[kc + 9] : 0.f;
                float v6 = (kc + 8 < K) ? pb[kc + 8] : 0.f;
                float v7 = (kc + 9 < K) ? pb[kc + 9] : 0.f;
                split2(v0, v1, ah[i][0], al[i][0]);
                split2(v2, v3, ah[i][1], al[i][1]);
                split2(v4, v5, ah[i][2], al[i][2]);
                split2(v6, v7, ah[i][3], al[i][3]);
            }
        }
        // ---- B fragments from pre-packed global (L1/L2 resident) ----
        const uint2* bhp = g_Bfh + ((size_t)t * NTILES + jgBase) * 32 + lane;
        const uint2* blp = g_Bfl + ((size_t)t * NTILES + jgBase) * 32 + lane;
#pragma unroll
        for (int j = 0; j < 8; j++) {
            uint2 bh = __ldg(&bhp[j * 32]);
            uint2 bl = __ldg(&blp[j * 32]);
#pragma unroll
            for (int i = 0; i < 2; i++) {
                mma16816(acc[i][j], al[i], bh.x, bh.y);
                mma16816(acc[i][j], ah[i], bl.x, bl.y);
                mma16816(acc[i][j], ah[i], bh.x, bh.y);
            }
        }
    }

    // ---- store: thread owns (row lq, row lq+8) x (cols lk..lk+1) per tile ----
#pragma unroll
    for (int i = 0; i < 2; i++) {
        int crow = rowBase + i * 16 + lq;
#pragma unroll
        for (int j = 0; j < 8; j++) {
            float* cp = C + (size_t)crow * NT + colHalf * 64 + j * 8 + lk;
            *reinterpret_cast<float2*>(cp) = make_float2(acc[i][j][0], acc[i][j][1]);
            *reinterpret_cast<float2*>(cp + (size_t)8 * NT) = make_float2(acc[i][j][2], acc[i][j][3]);
        }
    }
}

// ---------------- SpMM (CSR) + bias + ReLU : one warp per row ----------------
template <int F>
__global__ void spmm_relu_k(const float* __restrict__ bias) {
    constexpr int VEC = F / 32;
    int w = (blockIdx.x * blockDim.x + threadIdx.x) >> 5;
    if (w >= N_NODES) return;
    int lane = threadIdx.x & 31;

    float acc[VEC];
#pragma unroll
    for (int v = 0; v < VEC; v++) acc[v] = 0.f;

    int s = g_rowptr[w], e = g_rowptr[w + 1];
    const float* base = g_support;
    for (int j = s; j < e; j++) {
        int c = __ldg(&g_col[j]);
        float vv = __ldg(&g_val[j]);
        const float* p = base + (size_t)c * F + lane * VEC;
        if (VEC == 4) {
            float4 q = *reinterpret_cast<const float4*>(p);
            acc[0] += vv * q.x; acc[1] += vv * q.y;
            acc[2] += vv * q.z; acc[3] += vv * q.w;
        } else {
            float2 q = *reinterpret_cast<const float2*>(p);
            acc[0] += vv * q.x; acc[1] += vv * q.y;
        }
    }

    float* out = g_h + (size_t)w * F + lane * VEC;
    if (VEC == 4) {
        float4 b = *reinterpret_cast<const float4*>(bias + lane * 4);
        float4 r;
        r.x = fmaxf(acc[0] + b.x, 0.f);
        r.y = fmaxf(acc[1] + b.y, 0.f);
        r.z = fmaxf(acc[2] + b.z, 0.f);
        r.w = fmaxf(acc[3] + b.w, 0.f);
        *reinterpret_cast<float4*>(out) = r;
    } else {
        float2 b = *reinterpret_cast<const float2*>(bias + lane * 2);
        float2 r;
        r.x = fmaxf(acc[0] + b.x, 0.f);
        r.y = fmaxf(acc[1] + b.y, 0.f);
        *reinterpret_cast<float2*>(out) = r;
    }
}

// ---------------- column sums ----------------
__global__ void zero_colsum_k() {
    if (threadIdx.x < F_HID) g_colsum[threadIdx.x] = 0.f;
}
template <int F>
__global__ void colsum_k() {
    int f = threadIdx.x;
    float s = 0.f;
    for (int r = blockIdx.x; r < N_NODES; r += gridDim.x)
        s += g_h[(size_t)r * F + f];
    atomicAdd(&g_colsum[f], s);
}

// ---------------- PairNorm (PN-SI) ----------------
template <int F>
__global__ void pairnorm_k() {
    constexpr int VEC = F / 32;
    int w = (blockIdx.x * blockDim.x + threadIdx.x) >> 5;
    if (w >= N_NODES) return;
    int lane = threadIdx.x & 31;

    float v[VEC];
    const float* src = g_h + (size_t)w * F + lane * VEC;
    if (VEC == 4) {
        float4 q = *reinterpret_cast<const float4*>(src);
        v[0] = q.x; v[1] = q.y; v[2] = q.z; v[3] = q.w;
    } else {
        float2 q = *reinterpret_cast<const float2*>(src);
        v[0] = q.x; v[1] = q.y;
    }
    const float invN = 1.0f / (float)N_NODES;
    float ss = 0.f;
#pragma unroll
    for (int i = 0; i < VEC; i++) {
        float m = g_colsum[lane * VEC + i] * invN;
        v[i] -= m;
        ss += v[i] * v[i];
    }
#pragma unroll
    for (int off = 16; off > 0; off >>= 1)
        ss += __shfl_xor_sync(0xFFFFFFFFu, ss, off);
    float inv = 1.0f / sqrtf(EPS + ss);

    float* dst = g_x + (size_t)w * F + lane * VEC;
    if (VEC == 4) {
        float4 r; r.x = v[0] * inv; r.y = v[1] * inv; r.z = v[2] * inv; r.w = v[3] * inv;
        *reinterpret_cast<float4*>(dst) = r;
    } else {
        float2 r; r.x = v[0] * inv; r.y = v[1] * inv;
        *reinterpret_cast<float2*>(dst) = r;
    }
}

// ---------------- decode ----------------
__global__ void decode_k(const int* __restrict__ pos, const int* __restrict__ neg,
                         float* __restrict__ out) {
    int w = (blockIdx.x * blockDim.x + threadIdx.x) >> 5;
    if (w >= N_EDGES) return;
    int lane = threadIdx.x & 31;
    int s, d;
    if (w < N_POS) { s = pos[2 * w]; d = pos[2 * w + 1]; }
    else { int e = w - N_POS; s = neg[2 * e]; d = neg[2 * e + 1]; }
    float2 a = *reinterpret_cast<const float2*>(g_x + (size_t)s * F_OUT + lane * 2);
    float2 b = *reinterpret_cast<const float2*>(g_x + (size_t)d * F_OUT + lane * 2);
    float p = a.x * b.x + a.y * b.y;
#pragma unroll
    for (int off = 16; off > 0; off >>= 1)
        p += __shfl_xor_sync(0xFFFFFFFFu, p, off);
    if (lane == 0) out[w] = 1.0f / (1.0f + expf(-p));
}

// ---------------- launch ----------------
extern "C" void kernel_launch(void* const* d_in, const int* in_sizes, int n_in,
                              void* d_out, int out_size) {
    const float* in_feature = (const float*)d_in[0];
    const int*   adj_row    = (const int*)d_in[1];
    const int*   adj_col    = (const int*)d_in[2];
    const float* adj_val    = (const float*)d_in[3];
    const int*   pos_ei     = (const int*)d_in[4];
    const int*   neg_ei     = (const int*)d_in[5];
    const float* W0 = (const float*)d_in[6];
    const float* b0 = (const float*)d_in[7];
    const float* W1 = (const float*)d_in[8];
    const float* b1 = (const float*)d_in[9];
    const float* W2 = (const float*)d_in[10];
    const float* b2 = (const float*)d_in[11];
    float* out = (float*)d_out;

    float *g_x_p, *g_support_p;
    cudaGetSymbolAddress((void**)&g_x_p, g_x);
    cudaGetSymbolAddress((void**)&g_support_p, g_support);

    const int warp_grid = (N_NODES * 32 + 255) / 256;       // 12500

    // L0: M=100000 = 3125 row-tiles exactly; NT=128 -> 6250 warps
    const int w_l0 = 3125 * 2;
    // L1/L2: A = g_x padded to M_PAD = 3128 row-tiles (pad rows are zeros)
    const int w_l1 = 3128 * 2;
    const int w_l2 = 3128;

    // launch order: the big L0 GEMM sits at index 4 for ncu's capture window
    bsplit2_k<<<(T16_L0 * 16 * 32 + 255) / 256, 256>>>(W0, F_IN, F_HID, T16_L0);          // 1
    zero_cnt_k<<<(N_NODES + 255) / 256, 256>>>();                                          // 2
    hist_k<<<(N_NNZ + 255) / 256, 256>>>(adj_row);                                         // 3
    gemm_frag_k<F_HID><<<(w_l0 + 3) / 4, 128>>>(in_feature, g_support_p, F_IN, T16_L0, w_l0); // 4 (BIG)
    scanA_k<<<SCAN_NB, 1024>>>();                                                          // 5
    scanB_k<<<1, 32>>>();                                                                  // 6
    scanC_k<<<SCAN_NB, 1024>>>();                                                          // 7
    scatter_k<<<(N_NNZ + 255) / 256, 256>>>(adj_row, adj_col, adj_val);                    // 8

    // --- layer 0 tail ---
    spmm_relu_k<F_HID><<<warp_grid, 256>>>(b0);
    zero_colsum_k<<<1, 128>>>();
    colsum_k<F_HID><<<512, F_HID>>>();
    pairnorm_k<F_HID><<<warp_grid, 256>>>();

    // --- layer 1: g_x[*,128] @ W1[128,128] ---
    bsplit2_k<<<(8 * 16 * 32 + 255) / 256, 256>>>(W1, F_HID, F_HID, 8);
    gemm_frag_k<F_HID><<<(w_l1 + 3) / 4, 128>>>(g_x_p, g_support_p, F_HID, 8, w_l1);
    spmm_relu_k<F_HID><<<warp_grid, 256>>>(b1);
    zero_colsum_k<<<1, 128>>>();
    colsum_k<F_HID><<<512, F_HID>>>();
    pairnorm_k<F_HID><<<warp_grid, 256>>>();

    // --- layer 2: g_x[*,128] @ W2[128,64] ---
    bsplit2_k<<<(8 * 8 * 32 + 255) / 256, 256>>>(W2, F_HID, F_OUT, 8);
    gemm_frag_k<F_OUT><<<(w_l2 + 3) / 4, 128>>>(g_x_p, g_support_p, F_HID, 8, w_l2);
    spmm_relu_k<F_OUT><<<warp_grid, 256>>>(b2);
    zero_colsum_k<<<1, 128>>>();
    colsum_k<F_OUT><<<512, F_OUT>>>();
    pairnorm_k<F_OUT><<<warp_grid, 256>>>();

    // --- decode ---
    decode_k<<<(N_EDGES * 32 + 255) / 256, 256>>>(pos_ei, neg_ei, out);
}